// round 9
// baseline (speedup 1.0000x reference)
#include <cuda_runtime.h>
#include <math.h>

#define BATCH    4096
#define T        80
#define EMB      100
#define EMBP     128         // xs padded k-rows (zero-filled 100..127)
#define H        256
#define HS       36          // padded SMEM stride (multiple of 4 -> 16B-aligned rows)
#define KC       32          // k-chunk for streamed weight tiles
#define M2       32          // batch rows per block
#define NTHREADS 256

typedef unsigned long long u64;

union F4P { float4 f4; u64 p[2]; };

__device__ __forceinline__ u64 ffma2(u64 a, u64 b, u64 c) {
    u64 d;
    asm("fma.rn.f32x2 %0, %1, %2, %3;" : "=l"(d) : "l"(a), "l"(b), "l"(c));
    return d;
}
__device__ __forceinline__ u64 splat2(float x) {
    u64 d; asm("mov.b64 %0, {%1, %1};" : "=l"(d) : "f"(x)); return d;
}
__device__ __forceinline__ void unpack2(u64 p, float& lo, float& hi) {
    asm("mov.b64 {%0, %1}, %2;" : "=f"(lo), "=f"(hi) : "l"(p));
}

// acc[4 row-pairs][4 cols] += hs(k-major [nk][HS]) @ Wg(row-major, nk_w valid rows)
// nk is a multiple of KC. Double-buffered weight stream, ONE sync per tile
// (buffer overwritten at tile kt was last read at tile kt-2; tile kt-1's sync
// orders those reads before this store). Inner k-loop: distance-1 register
// prefetch so LDS latency overlaps the FFMA2 chain.
__device__ __forceinline__ void gemm_stream(
    const float* __restrict__ Wg, int nk, int nk_w,
    const float* __restrict__ hs,
    float* __restrict__ wbuf,
    u64 acc[4][4], int tid, int r0, int c0)
{
    const float4* W4 = (const float4*)Wg;
    const int nt = nk / KC;
    float4 pre[8];
#pragma unroll
    for (int j = 0; j < 8; ++j) {
        int q = tid + j * NTHREADS;
        pre[j] = ((q >> 6) < nk_w) ? W4[q] : make_float4(0.f, 0.f, 0.f, 0.f);
    }
#pragma unroll 1
    for (int kt = 0; kt < nt; ++kt) {
        float* buf = wbuf + (kt & 1) * (KC * H);
#pragma unroll
        for (int j = 0; j < 8; ++j)
            ((float4*)buf)[tid + j * NTHREADS] = pre[j];
        if (kt + 1 < nt) {
#pragma unroll
            for (int j = 0; j < 8; ++j) {
                int q = tid + j * NTHREADS;
                int row = (kt + 1) * KC + (q >> 6);
                pre[j] = (row < nk_w) ? W4[(kt + 1) * (KC * H / 4) + q]
                                      : make_float4(0.f, 0.f, 0.f, 0.f);
            }
        }
        __syncthreads();
        const float* hk = hs + kt * KC * HS;

        // ---- pipelined inner loop over KC k's ----
        F4P a0c, a1c, bc;
        a0c.f4 = *(const float4*)&hk[r0];
        a1c.f4 = *(const float4*)&hk[r0 + 4];
        bc.f4  = *(const float4*)&buf[c0];
#pragma unroll 8
        for (int kk = 0; kk < KC; ++kk) {
            F4P a0n, a1n, bn;
            if (kk + 1 < KC) {
                a0n.f4 = *(const float4*)&hk[(kk + 1) * HS + r0];
                a1n.f4 = *(const float4*)&hk[(kk + 1) * HS + r0 + 4];
                bn.f4  = *(const float4*)&buf[(kk + 1) * H + c0];
            }
            u64 bb[4] = { splat2(bc.f4.x), splat2(bc.f4.y),
                          splat2(bc.f4.z), splat2(bc.f4.w) };
            u64 ap[4] = { a0c.p[0], a0c.p[1], a1c.p[0], a1c.p[1] };
#pragma unroll
            for (int p = 0; p < 4; ++p)
#pragma unroll
                for (int j = 0; j < 4; ++j)
                    acc[p][j] = ffma2(ap[p], bb[j], acc[p][j]);
            if (kk + 1 < KC) { a0c = a0n; a1c = a1n; bc = bn; }
        }
    }
}

// tanh an acc tile and write it k-major into a state array (row-quad float4 STS)
__device__ __forceinline__ void tanh_store(u64 acc[4][4], float* __restrict__ st,
                                           int r0, int c0)
{
    float t[8][4];
#pragma unroll
    for (int p = 0; p < 4; ++p)
#pragma unroll
        for (int j = 0; j < 4; ++j) {
            float lo, hi; unpack2(acc[p][j], lo, hi);
            t[2 * p][j] = tanhf(lo); t[2 * p + 1][j] = tanhf(hi);
        }
#pragma unroll
    for (int j = 0; j < 4; ++j)
#pragma unroll
        for (int ii = 0; ii < 2; ++ii) {
            float4 v = make_float4(t[4 * ii + 0][j], t[4 * ii + 1][j],
                                   t[4 * ii + 2][j], t[4 * ii + 3][j]);
            *(float4*)&st[(c0 + j) * HS + r0 + 4 * ii] = v;
        }
}

__global__ __launch_bounds__(NTHREADS, 1)
void rnn_fused_kernel(const int*   __restrict__ inputs, // [BATCH][T]
                      const float* __restrict__ emb,    // [VOCAB][EMB]
                      const float* __restrict__ W1,     // [EMB][H]
                      const float* __restrict__ U1,     // [H][H]
                      const float* __restrict__ b1,     // [H]
                      const float* __restrict__ W2,     // [H][H]
                      const float* __restrict__ U2,     // [H][H]
                      const float* __restrict__ b2,     // [H]
                      float*       __restrict__ out)    // [BATCH][H]
{
    extern __shared__ float sm[];
    float* xs   = sm;                    // EMBP*HS = 4608 floats
    float* h1   = xs + EMBP * HS;        // H*HS    = 9216
    float* h2   = h1 + H * HS;           // H*HS    = 9216
    float* wbuf = h2 + H * HS;           // 2*KC*H  = 16384
    int*   toks = (int*)(wbuf + 2 * KC * H);   // M2*T  = 2560 ints

    const int tid = threadIdx.x;
    const int ty = tid >> 6, tx = tid & 63;
    const int r0 = ty * 8, c0 = tx * 4;
    const int bb = blockIdx.x * M2;

    // zero xs (incl. pad rows) and both states
    for (int i = tid; i < EMBP * HS + 2 * H * HS; i += NTHREADS) xs[i] = 0.f;
    // preload all tokens for this block: [M2][T]
    for (int i = tid; i < M2 * T; i += NTHREADS)
        toks[i] = inputs[(bb + i / T) * T + (i % T)];

    const float4 b1v = ((const float4*)b1)[tx];
    const float4 b2v = ((const float4*)b2)[tx];
    const u64 b1p[4] = { splat2(b1v.x), splat2(b1v.y), splat2(b1v.z), splat2(b1v.w) };
    const u64 b2p[4] = { splat2(b2v.x), splat2(b2v.y), splat2(b2v.z), splat2(b2v.w) };
    __syncthreads();

#pragma unroll 1
    for (int t = 0; t < T; ++t) {
        // ---- gather x_t : 32 rows x 25 float4 from emb, store k-major ----
        for (int i = tid; i < M2 * (EMB / 4); i += NTHREADS) {
            int r  = i / (EMB / 4);
            int kq = i % (EMB / 4);
            int tok = toks[r * T + t];
            float4 v = ((const float4*)emb)[tok * (EMB / 4) + kq];
            xs[(kq * 4 + 0) * HS + r] = v.x;
            xs[(kq * 4 + 1) * HS + r] = v.y;
            xs[(kq * 4 + 2) * HS + r] = v.z;
            xs[(kq * 4 + 3) * HS + r] = v.w;
        }
        __syncthreads();   // publish xs (and h2 from previous step)

        // ---- layer 1: acc = b1 + x@W1 + h1_old@U1 ----
        u64 acc[4][4];
#pragma unroll
        for (int p = 0; p < 4; ++p)
#pragma unroll
            for (int j = 0; j < 4; ++j) acc[p][j] = b1p[j];
        gemm_stream(W1, EMBP, EMB, xs, wbuf, acc, tid, r0, c0);
        gemm_stream(U1, H,    H,   h1, wbuf, acc, tid, r0, c0);

        __syncthreads();   // all threads done reading old h1
        tanh_store(acc, h1, r0, c0);
        __syncthreads();   // new h1 visible

        // ---- layer 2: acc2 = b2 + h1_new@W2 + h2_old@U2 ----
        u64 acc2[4][4];
#pragma unroll
        for (int p = 0; p < 4; ++p)
#pragma unroll
            for (int j = 0; j < 4; ++j) acc2[p][j] = b2p[j];
        gemm_stream(W2, H, H, h1, wbuf, acc2, tid, r0, c0);
        gemm_stream(U2, H, H, h2, wbuf, acc2, tid, r0, c0);

        __syncthreads();   // all threads done reading old h2
        if (t == T - 1) {
            float tt[8][4];
#pragma unroll
            for (int p = 0; p < 4; ++p)
#pragma unroll
                for (int j = 0; j < 4; ++j) {
                    float lo, hi; unpack2(acc2[p][j], lo, hi);
                    tt[2 * p][j]     = 1.f / (1.f + expf(-tanhf(lo)));
                    tt[2 * p + 1][j] = 1.f / (1.f + expf(-tanhf(hi)));
                }
#pragma unroll
            for (int i = 0; i < 8; ++i) {
                float4 o = make_float4(tt[i][0], tt[i][1], tt[i][2], tt[i][3]);
                *(float4*)&out[(bb + r0 + i) * H + c0] = o;
            }
        } else {
            tanh_store(acc2, h2, r0, c0);
            // new h2 is published by the sync after next step's gather
        }
    }
}

extern "C" void kernel_launch(void* const* d_in, const int* in_sizes, int n_in,
                              void* d_out, int out_size)
{
    const int*   inputs = (const int*)  d_in[0];
    const float* emb    = (const float*)d_in[1];
    const float* W1     = (const float*)d_in[2];
    const float* U1     = (const float*)d_in[3];
    const float* b1     = (const float*)d_in[4];
    const float* W2     = (const float*)d_in[5];
    const float* U2     = (const float*)d_in[6];
    const float* b2     = (const float*)d_in[7];
    float* out = (float*)d_out;

    const int smem_bytes =
        (EMBP * HS + 2 * H * HS + 2 * KC * H + M2 * T) * (int)sizeof(float); // 167936 B

    cudaFuncSetAttribute(rnn_fused_kernel,
                         cudaFuncAttributeMaxDynamicSharedMemorySize, smem_bytes);

    rnn_fused_kernel<<<BATCH / M2, NTHREADS, smem_bytes>>>(
        inputs, emb, W1, U1, b1, W2, U2, b2, out);
}

// round 10
// speedup vs baseline: 2.0614x; 2.0614x over previous
#include <cuda_runtime.h>
#include <math.h>

#define BATCH    4096
#define T        80
#define VOCAB    10000
#define EMB      100
#define H        256
#define HS       36          // padded SMEM stride for state tiles
#define KC       32          // k-chunk for streamed weight tiles
#define M2       32          // batch rows per block
#define NTHREADS 256

typedef unsigned long long u64;

// Precomputed embW[v][n] = b1[n] + sum_k emb[v][k] * W1[k][n]   (10.24 MB, L2-resident)
__device__ float g_embW[(size_t)VOCAB * H];

__device__ __forceinline__ u64 ffma2(u64 a, u64 b, u64 c) {
    u64 d;
    asm("fma.rn.f32x2 %0, %1, %2, %3;" : "=l"(d) : "l"(a), "l"(b), "l"(c));
    return d;
}
__device__ __forceinline__ u64 splat2(float x) {
    u64 d; asm("mov.b64 %0, {%1, %1};" : "=l"(d) : "f"(x)); return d;
}
__device__ __forceinline__ u64 pack2(float lo, float hi) {
    u64 d; asm("mov.b64 %0, {%1, %2};" : "=l"(d) : "f"(lo), "f"(hi)); return d;
}
__device__ __forceinline__ void unpack2(u64 p, float& lo, float& hi) {
    asm("mov.b64 {%0, %1}, %2;" : "=f"(lo), "=f"(hi) : "l"(p));
}
// fast tanh via expf: rel err ~1e-6, ~6 instrs
__device__ __forceinline__ float tanh_e(float x) {
    float e = __expf(-2.f * fabsf(x));
    float r = __fdividef(1.f - e, 1.f + e);
    return copysignf(r, x);
}

// ============================================================================
// embW precompute: grid ceil(VOCAB/32), 256 thr. embW = b1 + emb @ W1.
// ============================================================================
__global__ __launch_bounds__(NTHREADS, 1)
void embw_kernel(const float* __restrict__ emb, const float* __restrict__ W1,
                 const float* __restrict__ b1)
{
    extern __shared__ float sm[];
    float* W1s = sm;                 // EMB*H  = 25600 floats
    float* xs  = W1s + EMB * H;      // EMB*HS =  3600 floats

    const int tid = threadIdx.x;
    const int ty = tid >> 6, tx = tid & 63;
    const int r0 = ty * 8, c0 = tx * 4;
    const int v0 = blockIdx.x * M2;

    // W1 -> smem (6400 float4, 25/thread)
#pragma unroll
    for (int j = 0; j < (EMB * H / 4) / NTHREADS; ++j)
        ((float4*)W1s)[tid + j * NTHREADS] = ((const float4*)W1)[tid + j * NTHREADS];
    // zero xs (covers out-of-vocab tail rows)
    for (int i = tid; i < EMB * HS; i += NTHREADS) xs[i] = 0.f;
    __syncthreads();
    // gather emb rows k-major
    for (int i = tid; i < M2 * (EMB / 4); i += NTHREADS) {
        int r = i / (EMB / 4), q = i % (EMB / 4);
        int v = v0 + r;
        if (v < VOCAB) {
            float4 x = ((const float4*)emb)[v * (EMB / 4) + q];
            xs[(4 * q + 0) * HS + r] = x.x;
            xs[(4 * q + 1) * HS + r] = x.y;
            xs[(4 * q + 2) * HS + r] = x.z;
            xs[(4 * q + 3) * HS + r] = x.w;
        }
    }
    const float4 b1v = ((const float4*)b1)[tx];
    __syncthreads();

    u64 acc[4][4];
    const u64 bp[4] = { splat2(b1v.x), splat2(b1v.y), splat2(b1v.z), splat2(b1v.w) };
#pragma unroll
    for (int p = 0; p < 4; ++p)
#pragma unroll
        for (int j = 0; j < 4; ++j) acc[p][j] = bp[j];

#pragma unroll 4
    for (int k = 0; k < EMB; ++k) {
        float4 a0 = *(const float4*)&xs[k * HS + r0];
        float4 a1 = *(const float4*)&xs[k * HS + r0 + 4];
        float4 b  = *(const float4*)&W1s[k * H + c0];
        u64 ap[4] = { pack2(a0.x, a0.y), pack2(a0.z, a0.w),
                      pack2(a1.x, a1.y), pack2(a1.z, a1.w) };
        u64 bb[4] = { splat2(b.x), splat2(b.y), splat2(b.z), splat2(b.w) };
#pragma unroll
        for (int p = 0; p < 4; ++p)
#pragma unroll
            for (int j = 0; j < 4; ++j)
                acc[p][j] = ffma2(ap[p], bb[j], acc[p][j]);
    }
    // store rows v0+r0 .. v0+r0+7
#pragma unroll
    for (int i = 0; i < 8; ++i) {
        int v = v0 + r0 + i;
        if (v < VOCAB) {
            float t0, t1, t2, t3, lo, hi;
            unpack2(acc[i >> 1][0], lo, hi); t0 = (i & 1) ? hi : lo;
            unpack2(acc[i >> 1][1], lo, hi); t1 = (i & 1) ? hi : lo;
            unpack2(acc[i >> 1][2], lo, hi); t2 = (i & 1) ? hi : lo;
            unpack2(acc[i >> 1][3], lo, hi); t3 = (i & 1) ? hi : lo;
            *(float4*)&g_embW[(size_t)v * H + c0] = make_float4(t0, t1, t2, t3);
        }
    }
}

// ============================================================================
// Recurrent GEMM: acc += hs(k-major [256][HS]) @ Wg([256][256] row-major).
// Exactly 8 KC=32 tiles, double-buffered, ONE sync per tile (R4-proven).
// ============================================================================
__device__ __forceinline__ void gemm_stream(
    const float* __restrict__ Wg, const float* __restrict__ hs,
    float* __restrict__ wbuf, u64 acc[4][4], int tid, int r0, int c0)
{
    const float4* W4 = (const float4*)Wg;
    float4 pre[8];
#pragma unroll
    for (int j = 0; j < 8; ++j) pre[j] = W4[tid + j * NTHREADS];

#pragma unroll 1
    for (int kt = 0; kt < H / KC; ++kt) {
        float* buf = wbuf + (kt & 1) * (KC * H);
#pragma unroll
        for (int j = 0; j < 8; ++j)
            ((float4*)buf)[tid + j * NTHREADS] = pre[j];
        if (kt + 1 < H / KC) {
#pragma unroll
            for (int j = 0; j < 8; ++j)
                pre[j] = W4[(kt + 1) * (KC * H / 4) + tid + j * NTHREADS];
        }
        __syncthreads();
        const float* hk = hs + kt * KC * HS;
#pragma unroll 8
        for (int kk = 0; kk < KC; ++kk) {
            float4 a0 = *(const float4*)&hk[kk * HS + r0];
            float4 a1 = *(const float4*)&hk[kk * HS + r0 + 4];
            float4 b  = *(const float4*)&buf[kk * H + c0];
            u64 ap[4] = { pack2(a0.x, a0.y), pack2(a0.z, a0.w),
                          pack2(a1.x, a1.y), pack2(a1.z, a1.w) };
            u64 bb[4] = { splat2(b.x), splat2(b.y), splat2(b.z), splat2(b.w) };
#pragma unroll
            for (int p = 0; p < 4; ++p)
#pragma unroll
                for (int j = 0; j < 4; ++j)
                    acc[p][j] = ffma2(ap[p], bb[j], acc[p][j]);
        }
    }
}

__device__ __forceinline__ void tanh_store(u64 acc[4][4], float* __restrict__ st,
                                           int r0, int c0)
{
    float t[8][4];
#pragma unroll
    for (int p = 0; p < 4; ++p)
#pragma unroll
        for (int j = 0; j < 4; ++j) {
            float lo, hi; unpack2(acc[p][j], lo, hi);
            t[2 * p][j] = tanh_e(lo); t[2 * p + 1][j] = tanh_e(hi);
        }
#pragma unroll
    for (int j = 0; j < 4; ++j)
#pragma unroll
        for (int ii = 0; ii < 2; ++ii)
            *(float4*)&st[(c0 + j) * HS + r0 + 4 * ii] =
                make_float4(t[4 * ii + 0][j], t[4 * ii + 1][j],
                            t[4 * ii + 2][j], t[4 * ii + 3][j]);
}

__global__ __launch_bounds__(NTHREADS, 1)
void rnn_fused_kernel(const int*   __restrict__ inputs,
                      const float* __restrict__ U1,
                      const float* __restrict__ W2,
                      const float* __restrict__ U2,
                      const float* __restrict__ b2,
                      float*       __restrict__ out)
{
    extern __shared__ float sm[];
    float* h1   = sm;                    // H*HS   = 9216 floats
    float* h2   = h1 + H * HS;           // H*HS   = 9216
    float* wbuf = h2 + H * HS;           // 2*KC*H = 16384
    int*   toks = (int*)(wbuf + 2 * KC * H);   // M2*T = 2560 ints

    const int tid = threadIdx.x;
    const int ty = tid >> 6, tx = tid & 63;
    const int r0 = ty * 8, c0 = tx * 4;
    const int bb = blockIdx.x * M2;

    for (int i = tid; i < 2 * H * HS; i += NTHREADS) h1[i] = 0.f;
    for (int i = tid; i < M2 * T; i += NTHREADS)
        toks[i] = inputs[(bb + i / T) * T + (i % T)];

    const float4 b2v = ((const float4*)b2)[tx];
    const u64 b2p[4] = { splat2(b2v.x), splat2(b2v.y), splat2(b2v.z), splat2(b2v.w) };
    __syncthreads();

#pragma unroll 1
    for (int t = 0; t < T; ++t) {
        // ---- layer 1: acc = embW[tok] (has b1 baked) + h1_old@U1 ----
        float4 xv[8];
#pragma unroll
        for (int i = 0; i < 8; ++i) {
            int tok = toks[(r0 + i) * T + t];
            xv[i] = *(const float4*)&g_embW[(size_t)tok * H + c0];
        }
        u64 acc[4][4];
#pragma unroll
        for (int p = 0; p < 4; ++p) {
            const float* lo = (const float*)&xv[2 * p];
            const float* hi = (const float*)&xv[2 * p + 1];
#pragma unroll
            for (int j = 0; j < 4; ++j) acc[p][j] = pack2(lo[j], hi[j]);
        }
        gemm_stream(U1, h1, wbuf, acc, tid, r0, c0);

        __syncthreads();                 // all threads done reading old h1
        tanh_store(acc, h1, r0, c0);
        __syncthreads();                 // new h1 visible

        // ---- layer 2: acc2 = b2 + h1_new@W2 + h2_old@U2 ----
        u64 acc2[4][4];
#pragma unroll
        for (int p = 0; p < 4; ++p)
#pragma unroll
            for (int j = 0; j < 4; ++j) acc2[p][j] = b2p[j];
        gemm_stream(W2, h1, wbuf, acc2, tid, r0, c0);
        gemm_stream(U2, h2, wbuf, acc2, tid, r0, c0);

        __syncthreads();                 // all threads done reading old h2
        if (t == T - 1) {
#pragma unroll
            for (int i = 0; i < 8; ++i) {
                float v[4];
#pragma unroll
                for (int j = 0; j < 4; ++j) {
                    float lo, hi; unpack2(acc2[i >> 1][j], lo, hi);
                    float x = tanh_e((i & 1) ? hi : lo);
                    v[j] = __fdividef(1.f, 1.f + __expf(-x));
                }
                *(float4*)&out[(bb + r0 + i) * H + c0] =
                    make_float4(v[0], v[1], v[2], v[3]);
            }
        } else {
            tanh_store(acc2, h2, r0, c0);
            // publish of new h2 is covered by next step's gemm tile-syncs
        }
    }
}

extern "C" void kernel_launch(void* const* d_in, const int* in_sizes, int n_in,
                              void* d_out, int out_size)
{
    const int*   inputs = (const int*)  d_in[0];
    const float* emb    = (const float*)d_in[1];
    const float* W1     = (const float*)d_in[2];
    const float* U1     = (const float*)d_in[3];
    const float* b1     = (const float*)d_in[4];
    const float* W2     = (const float*)d_in[5];
    const float* U2     = (const float*)d_in[6];
    const float* b2     = (const float*)d_in[7];
    float* out = (float*)d_out;

    const int smem_embw = (EMB * H + EMB * HS) * (int)sizeof(float);            // 116800
    const int smem_main = (2 * H * HS + 2 * KC * H + M2 * T) * (int)sizeof(float); // 149504

    cudaFuncSetAttribute(embw_kernel,
                         cudaFuncAttributeMaxDynamicSharedMemorySize, smem_embw);
    cudaFuncSetAttribute(rnn_fused_kernel,
                         cudaFuncAttributeMaxDynamicSharedMemorySize, smem_main);

    embw_kernel<<<(VOCAB + M2 - 1) / M2, NTHREADS, smem_embw>>>(emb, W1, b1);
    rnn_fused_kernel<<<BATCH / M2, NTHREADS, smem_main>>>(
        inputs, U1, W2, U2, b2, out);
}